// round 4
// baseline (speedup 1.0000x reference)
#include <cuda_runtime.h>
#include <cstdint>

#define BB 16
#define NN 25200
#define NCLS 80
#define PSTR 85
#define MAX_DET 300
#define M_TGT 50
#define CONF_THRES 0.8f
#define NMS_THRES 0.4f
#define CAND_MAX 12288
#define NBINS 512
#define SURV_MAX 2048
#define KW 10   // ceil(300/32) words

// ---- global scratch (no allocation allowed) ----
__device__ int      g_cand_count[BB];
__device__ int      g_hist[BB][NBINS];
__device__ float    g_cand_score[BB][CAND_MAX];
__device__ unsigned g_cand_meta[BB][CAND_MAX];

__device__ __forceinline__ int score_bin(float sc) {
    int b = (int)((sc - CONF_THRES) * (NBINS / 0.2f));
    if (b < 0) b = 0;
    if (b >= NBINS) b = NBINS - 1;
    return b;
}

// ---- Kernel A: warp per anchor; redux-based argmax (lowest idx on tie) ----
__global__ void __launch_bounds__(256) score_kernel(const float* __restrict__ preds) {
    int gwarp = (blockIdx.x * blockDim.x + threadIdx.x) >> 5;
    int lane  = threadIdx.x & 31;
    if (gwarp >= BB * NN) return;   // warp-uniform exit
    int b = gwarp / NN;
    int n = gwarp - b * NN;
    const float* p = preds + (size_t)gwarp * PSTR;

    float obj = __ldg(p + 4);
    // positive floats: uint bit order == float order (values are uniform in [0,1))
    unsigned b0 = __float_as_uint(__ldg(p + 5 + lane));                    // cls  0..31
    unsigned b1 = __float_as_uint(__ldg(p + 5 + 32 + lane));               // cls 32..63
    unsigned b2 = (lane < NCLS - 64) ? __float_as_uint(__ldg(p + 5 + 64 + lane)) : 0u; // 64..79

    unsigned mymax = max(b0, max(b1, b2));
    unsigned mx = __reduce_max_sync(0xFFFFFFFFu, mymax);

    // per-lane lowest matching class index (check in ascending-index order)
    unsigned cand = 0xFFFFu;
    if (b2 == mx) cand = lane + 64;
    if (b1 == mx) cand = lane + 32;
    if (b0 == mx) cand = lane;
    unsigned bi = __reduce_min_sync(0xFFFFFFFFu, cand);

    if (lane == 0) {
        float best = __uint_as_float(mx);
        float score = obj * best;
        if (score > CONF_THRES) {
            int pos = atomicAdd(&g_cand_count[b], 1);
            if (pos < CAND_MAX) {
                g_cand_score[b][pos] = score;
                g_cand_meta[b][pos]  = (unsigned)n | (bi << 16);
            }
            atomicAdd(&g_hist[b][score_bin(score)], 1);
        }
    }
}

// ---- Kernel B: per-batch top-300 + NMS + targets + output ----
__global__ void __launch_bounds__(512) select_nms_kernel(
    const float* __restrict__ preds,
    const float* __restrict__ tgt,
    const int*   __restrict__ tlen,
    float* __restrict__ out)
{
    __shared__ float    s_score[SURV_MAX];
    __shared__ unsigned s_meta[SURV_MAX];
    __shared__ int      s_hist[NBINS];
    __shared__ int      s_cnt, s_cutoff;
    __shared__ float    t_score[MAX_DET];
    __shared__ unsigned t_meta[MAX_DET];
    __shared__ float    t_box[MAX_DET][4];
    __shared__ float    t_area[MAX_DET];
    __shared__ unsigned s_mask[MAX_DET][KW];
    __shared__ unsigned s_keepw[KW];

    const int b   = blockIdx.x;
    const int tid = threadIdx.x;
    const int nt  = blockDim.x;

    for (int i = tid; i < NBINS; i += nt) s_hist[i] = g_hist[b][i];
    if (tid == 0) s_cnt = 0;
    __syncthreads();

    if (tid == 0) {
        int acc = 0, cut = 0;
        for (int i = NBINS - 1; i >= 0; --i) {
            acc += s_hist[i];
            if (acc >= MAX_DET) { cut = i; break; }
        }
        s_cutoff = cut;
    }
    __syncthreads();
    const int cutoff = s_cutoff;

    int C = g_cand_count[b];
    if (C > CAND_MAX) C = CAND_MAX;
    for (int i = tid; i < C; i += nt) {
        float sc = g_cand_score[b][i];
        if (score_bin(sc) >= cutoff) {
            int p = atomicAdd(&s_cnt, 1);
            if (p < SURV_MAX) { s_score[p] = sc; s_meta[p] = g_cand_meta[b][i]; }
        }
    }
    __syncthreads();
    int S = s_cnt; if (S > SURV_MAX) S = SURV_MAX;
    const int nval = (S < MAX_DET) ? S : MAX_DET;

    for (int i = tid; i < MAX_DET; i += nt) { t_score[i] = 0.0f; t_meta[i] = 0u; }
    __syncthreads();

    // exact stable rank (desc by score, asc by anchor on ties) == jax.lax.top_k order
    for (int i = tid; i < S; i += nt) {
        float v = s_score[i];
        unsigned me = s_meta[i];
        int an = (int)(me & 0xFFFFu);
        int r = 0;
        for (int j = 0; j < S; j++) {       // s_score[j]/s_meta[j] broadcast reads
            float u = s_score[j];
            int aj = (int)(s_meta[j] & 0xFFFFu);
            r += (u > v) || (u == v && aj < an);
        }
        if (r < MAX_DET) { t_score[r] = v; t_meta[r] = me; }
    }
    __syncthreads();

    // gather boxes of top detections, cxcywh -> xyxy (x2 = x1 + w to match ref)
    for (int i = tid; i < nval; i += nt) {
        int an = (int)(t_meta[i] & 0xFFFFu);
        const float* p = preds + ((size_t)b * NN + an) * PSTR;
        float cx = p[0], cy = p[1], w = p[2], h = p[3];
        float x1 = cx - 0.5f * w;
        float y1 = cy - 0.5f * h;
        float x2 = x1 + w;
        float y2 = y1 + h;
        t_box[i][0] = x1; t_box[i][1] = y1; t_box[i][2] = x2; t_box[i][3] = y2;
        t_area[i] = fmaxf(x2 - x1, 0.0f) * fmaxf(y2 - y1, 0.0f);
    }
    __syncthreads();

    // suppression bitmask, TRANSPOSED mapping: lanes share w, consecutive i.
    // inner-loop j = 32w+k is warp-uniform -> all [j] smem reads are broadcasts.
    for (int t = tid; t < KW * MAX_DET; t += nt) {
        int w = t / MAX_DET;
        int i = t - w * MAX_DET;
        unsigned m = 0u;
        if (i < nval) {
            float x1i = t_box[i][0], y1i = t_box[i][1];
            float x2i = t_box[i][2], y2i = t_box[i][3];
            float ai  = t_area[i];
            unsigned li = t_meta[i] >> 16;
            int jbase = w << 5;
            #pragma unroll 4
            for (int k = 0; k < 32; k++) {
                int j = jbase + k;
                if (j < nval) {
                    float bx1 = t_box[j][0], by1 = t_box[j][1];   // broadcast
                    float bx2 = t_box[j][2], by2 = t_box[j][3];   // broadcast
                    float aj  = t_area[j];                        // broadcast
                    unsigned lj = t_meta[j] >> 16;                // broadcast
                    float xx1 = fmaxf(x1i, bx1);
                    float yy1 = fmaxf(y1i, by1);
                    float xx2 = fminf(x2i, bx2);
                    float yy2 = fminf(y2i, by2);
                    float inter = fmaxf(xx2 - xx1, 0.0f) * fmaxf(yy2 - yy1, 0.0f);
                    float iou = inter / (ai + aj - inter + 1e-9f);
                    if ((j > i) && (lj == li) && (iou > NMS_THRES)) m |= (1u << k);
                }
            }
        }
        s_mask[i][w] = m;
    }
    __syncthreads();

    // sequential greedy pass on warp 0, removed-words in registers
    if (tid < 32) {
        unsigned removed = 0u;
        for (int i = 0; i < nval; i++) {
            int w = i >> 5;
            int alive = (tid == w) ? (int)(!((removed >> (i & 31)) & 1u)) : 0;
            alive = __shfl_sync(0xFFFFFFFFu, alive, w);
            if (alive) {
                unsigned m = (tid < KW) ? s_mask[i][tid] : 0u;
                removed |= m;
            }
        }
        if (tid < KW) s_keepw[tid] = ~removed;
    }
    __syncthreads();

    // ---- outputs (float32, tree-flatten order) ----
    const int OFF_PB = 0;
    const int OFF_PS = BB * MAX_DET * 4;           // 19200
    const int OFF_PL = OFF_PS + BB * MAX_DET;      // 24000
    const int OFF_PV = OFF_PL + BB * MAX_DET;      // 28800
    const int OFF_TB = OFF_PV + BB * MAX_DET;      // 33600
    const int OFF_TS = OFF_TB + BB * M_TGT * 4;    // 36800
    const int OFF_TL = OFF_TS + BB * M_TGT;        // 37600
    const int OFF_TV = OFF_TL + BB * M_TGT;        // 38400

    for (int i = tid; i < MAX_DET; i += nt) {
        bool kp = (i < nval) && ((s_keepw[i >> 5] >> (i & 31)) & 1u);
        float* pb = out + OFF_PB + ((size_t)b * MAX_DET + i) * 4;
        pb[0] = kp ? t_box[i][0] : 0.0f;
        pb[1] = kp ? t_box[i][1] : 0.0f;
        pb[2] = kp ? t_box[i][2] : 0.0f;
        pb[3] = kp ? t_box[i][3] : 0.0f;
        out[OFF_PS + b * MAX_DET + i] = kp ? t_score[i] : 0.0f;
        out[OFF_PL + b * MAX_DET + i] = kp ? (float)(t_meta[i] >> 16) : -1.0f;
        out[OFF_PV + b * MAX_DET + i] = kp ? 1.0f : 0.0f;
    }

    // targets
    int L = tlen[b];
    for (int m = tid; m < M_TGT; m += nt) {
        const float* q = tgt + ((size_t)b * M_TGT + m) * 6;
        bool v = (m < L);
        float cx = q[0], cy = q[1], w = q[2], h = q[3], sc = q[4], lb = q[5];
        float x1 = cx - 0.5f * w;
        float y1 = cy - 0.5f * h;
        float* tb = out + OFF_TB + ((size_t)b * M_TGT + m) * 4;
        tb[0] = v ? x1 : 0.0f;
        tb[1] = v ? y1 : 0.0f;
        tb[2] = v ? (x1 + w) : 0.0f;
        tb[3] = v ? (y1 + h) : 0.0f;
        out[OFF_TS + b * M_TGT + m] = v ? sc : 0.0f;
        out[OFF_TL + b * M_TGT + m] = v ? lb : -1.0f;
        out[OFF_TV + b * M_TGT + m] = v ? 1.0f : 0.0f;
    }
}

extern "C" void kernel_launch(void* const* d_in, const int* in_sizes, int n_in,
                              void* d_out, int out_size) {
    const float* preds = (const float*)d_in[0];
    const float* tgt   = (const float*)d_in[1];
    const int*   tlen  = (const int*)d_in[2];
    float* out = (float*)d_out;

    // zero per-launch scratch via memset (graph-capturable, no extra kernel)
    void* p_cnt = nullptr;
    void* p_hist = nullptr;
    cudaGetSymbolAddress(&p_cnt,  g_cand_count);
    cudaGetSymbolAddress(&p_hist, g_hist);
    cudaMemsetAsync(p_cnt,  0, sizeof(int) * BB);
    cudaMemsetAsync(p_hist, 0, sizeof(int) * BB * NBINS);

    score_kernel<<<(BB * NN + 7) / 8, 256>>>(preds);   // 403200 warps, 8/block
    select_nms_kernel<<<BB, 512>>>(preds, tgt, tlen, out);
}

// round 5
// speedup vs baseline: 1.3078x; 1.3078x over previous
#include <cuda_runtime.h>
#include <cstdint>

#define BB 16
#define NN 25200
#define NCLS 80
#define PSTR 85
#define MAX_DET 300
#define M_TGT 50
#define CONF_THRES 0.8f
#define NMS_THRES 0.4f
#define CAND_MAX 12288
#define NBINS 512
#define SURV_MAX 2048
#define KW 10   // ceil(300/32)
#define ANCH_PER_BLK 128
#define SCORE_THREADS 256
#define NMS_THREADS 1024

// ---- global scratch (no allocation allowed) ----
__device__ int      g_cand_count[BB];
__device__ int      g_hist[BB][NBINS];
__device__ float    g_cand_score[BB][CAND_MAX];
__device__ unsigned g_cand_meta[BB][CAND_MAX];

__device__ __forceinline__ int score_bin(float sc) {
    int b = (int)((sc - CONF_THRES) * (NBINS / 0.2f));
    if (b < 0) b = 0;
    if (b >= NBINS) b = NBINS - 1;
    return b;
}

// ---- Kernel A: smem-staged streaming scan; warp-per-anchor reduction ----
__global__ void __launch_bounds__(SCORE_THREADS) score_kernel(const float* __restrict__ preds) {
    __shared__ float sp[ANCH_PER_BLK * PSTR];   // 10880 floats = 43520 B
    const int tid = threadIdx.x;

    // perfectly-coalesced float4 stream: 128*85 floats, offset divisible by 4
    const float4* src = (const float4*)(preds + (size_t)blockIdx.x * (ANCH_PER_BLK * PSTR));
    float4* dst = (float4*)sp;
    const int n4 = ANCH_PER_BLK * PSTR / 4;     // 2720
    #pragma unroll 4
    for (int i = tid; i < n4; i += SCORE_THREADS) dst[i] = src[i];
    __syncthreads();

    const int wid = tid >> 5, lane = tid & 31;
    const int abase = wid * (ANCH_PER_BLK / 8);   // 16 anchors per warp
    for (int a = abase; a < abase + ANCH_PER_BLK / 8; a++) {
        const float* p = sp + a * PSTR;
        float obj = p[4];                                   // broadcast
        unsigned m0 = __float_as_uint(p[5 + lane]);         // cls  0..31
        unsigned m1 = __float_as_uint(p[37 + lane]);        // cls 32..63
        unsigned m2 = (lane < 16) ? __float_as_uint(p[69 + lane]) : 0u; // 64..79
        // positive floats: uint order == float order
        unsigned loc = max(m0, max(m1, m2));
        unsigned mx = __reduce_max_sync(0xFFFFFFFFu, loc);
        float score = obj * __uint_as_float(mx);
        if (score > CONF_THRES) {                 // warp-uniform, rare (~19%)
            unsigned cand = 0xFFFFu;
            if (m2 == mx) cand = lane + 64;
            if (m1 == mx) cand = lane + 32;
            if (m0 == mx) cand = lane;            // lowest index wins on tie
            unsigned bi = __reduce_min_sync(0xFFFFFFFFu, cand);
            if (lane == 0) {
                int anchor = blockIdx.x * ANCH_PER_BLK + a;
                int b = anchor / NN;
                int n = anchor - b * NN;
                int pos = atomicAdd(&g_cand_count[b], 1);
                if (pos < CAND_MAX) {
                    g_cand_score[b][pos] = score;
                    g_cand_meta[b][pos]  = (unsigned)n | (bi << 16);
                }
                atomicAdd(&g_hist[b][score_bin(score)], 1);
            }
        }
    }
}

// ---- Kernel B: per-batch top-300 + NMS + targets + output ----
__global__ void __launch_bounds__(NMS_THREADS) select_nms_kernel(
    const float* __restrict__ preds,
    const float* __restrict__ tgt,
    const int*   __restrict__ tlen,
    float* __restrict__ out)
{
    __shared__ float    s_score[SURV_MAX];
    __shared__ unsigned s_meta[SURV_MAX];
    __shared__ int      s_hist[NBINS];
    __shared__ int      s_cnt, s_cutoff;
    __shared__ float    t_score[MAX_DET];
    __shared__ unsigned t_meta[MAX_DET];
    __shared__ float    t_box[MAX_DET][4];
    __shared__ float    t_area[MAX_DET];
    __shared__ unsigned s_mask[MAX_DET][KW];
    __shared__ unsigned s_keepw[KW];

    const int b   = blockIdx.x;
    const int tid = threadIdx.x;
    const int nt  = blockDim.x;

    for (int i = tid; i < NBINS; i += nt) s_hist[i] = g_hist[b][i];
    if (tid == 0) s_cnt = 0;
    __syncthreads();

    if (tid == 0) {
        int acc = 0, cut = 0;
        for (int i = NBINS - 1; i >= 0; --i) {
            acc += s_hist[i];
            if (acc >= MAX_DET) { cut = i; break; }
        }
        s_cutoff = cut;
    }
    __syncthreads();
    const int cutoff = s_cutoff;

    int C = g_cand_count[b];
    if (C > CAND_MAX) C = CAND_MAX;
    for (int i = tid; i < C; i += nt) {
        float sc = g_cand_score[b][i];
        if (score_bin(sc) >= cutoff) {
            int p = atomicAdd(&s_cnt, 1);
            if (p < SURV_MAX) { s_score[p] = sc; s_meta[p] = g_cand_meta[b][i]; }
        }
    }
    __syncthreads();
    int S = s_cnt; if (S > SURV_MAX) S = SURV_MAX;
    const int nval = (S < MAX_DET) ? S : MAX_DET;

    for (int i = tid; i < MAX_DET; i += nt) { t_score[i] = 0.0f; t_meta[i] = 0u; }
    __syncthreads();

    // exact stable rank (desc score, asc anchor on ties) == jax.lax.top_k order
    for (int i = tid; i < S; i += nt) {
        float v = s_score[i];
        unsigned me = s_meta[i];
        int an = (int)(me & 0xFFFFu);
        int r = 0;
        for (int j = 0; j < S; j++) {
            float u = s_score[j];
            int aj = (int)(s_meta[j] & 0xFFFFu);
            r += (u > v) || (u == v && aj < an);
        }
        if (r < MAX_DET) { t_score[r] = v; t_meta[r] = me; }
    }
    __syncthreads();

    // gather boxes, cxcywh -> xyxy (x2 = x1 + w to match ref bits)
    for (int i = tid; i < nval; i += nt) {
        int an = (int)(t_meta[i] & 0xFFFFu);
        const float* p = preds + ((size_t)b * NN + an) * PSTR;
        float cx = p[0], cy = p[1], w = p[2], h = p[3];
        float x1 = cx - 0.5f * w;
        float y1 = cy - 0.5f * h;
        float x2 = x1 + w;
        float y2 = y1 + h;
        t_box[i][0] = x1; t_box[i][1] = y1; t_box[i][2] = x2; t_box[i][3] = y2;
        t_area[i] = fmaxf(x2 - x1, 0.0f) * fmaxf(y2 - y1, 0.0f);
    }
    __syncthreads();

    // suppression bitmask: transposed mapping (lanes: same w, consecutive i)
    // + warp-uniform branch skips (word-level j>i skip, per-k label ballot).
    const int NTASK_PAD = ((KW * MAX_DET + NMS_THREADS - 1) / NMS_THREADS) * NMS_THREADS;
    for (int t0 = tid; t0 < NTASK_PAD; t0 += nt) {
        bool tv = (t0 < KW * MAX_DET);
        int w = tv ? (t0 / MAX_DET) : 0;
        int i = tv ? (t0 - w * MAX_DET) : 0;
        int jbase = w << 5;
        unsigned m = 0u;
        bool lane_live = tv && (i < nval);
        // any lane with possible j>i in this word?
        bool canwork = lane_live && (i < jbase + 31) ;
        if (__ballot_sync(0xFFFFFFFFu, canwork)) {
            float x1i = lane_live ? t_box[i][0] : 0.0f;
            float y1i = lane_live ? t_box[i][1] : 0.0f;
            float x2i = lane_live ? t_box[i][2] : 0.0f;
            float y2i = lane_live ? t_box[i][3] : 0.0f;
            float ai  = lane_live ? t_area[i]   : 0.0f;
            unsigned li = lane_live ? (t_meta[i] >> 16) : 0xFFFFFFFFu;
            #pragma unroll 4
            for (int k = 0; k < 32; k++) {
                int j = jbase + k;
                bool jv = (j < nval);
                unsigned lj = jv ? (t_meta[j] >> 16) : 0xFFFFFFFEu;   // broadcast
                bool need = lane_live && jv && (j > i) && (lj == li);
                if (__ballot_sync(0xFFFFFFFFu, need)) {   // skip IoU when no lane matches
                    float bx1 = t_box[j][0], by1 = t_box[j][1];       // broadcast
                    float bx2 = t_box[j][2], by2 = t_box[j][3];
                    float aj  = t_area[j];
                    float xx1 = fmaxf(x1i, bx1);
                    float yy1 = fmaxf(y1i, by1);
                    float xx2 = fminf(x2i, bx2);
                    float yy2 = fminf(y2i, by2);
                    float inter = fmaxf(xx2 - xx1, 0.0f) * fmaxf(yy2 - yy1, 0.0f);
                    float iou = inter / (ai + aj - inter + 1e-9f);
                    if (need && iou > NMS_THRES) m |= (1u << k);
                }
            }
        }
        if (tv) s_mask[i][w] = m;
    }
    __syncthreads();

    // sequential greedy pass on warp 0, removed-words in registers
    if (tid < 32) {
        unsigned removed = 0u;
        for (int i = 0; i < nval; i++) {
            int w = i >> 5;
            int alive = (tid == w) ? (int)(!((removed >> (i & 31)) & 1u)) : 0;
            alive = __shfl_sync(0xFFFFFFFFu, alive, w);
            if (alive) {
                unsigned m = (tid < KW) ? s_mask[i][tid] : 0u;
                removed |= m;
            }
        }
        if (tid < KW) s_keepw[tid] = ~removed;
    }
    __syncthreads();

    // ---- outputs (float32, tree-flatten order) ----
    const int OFF_PB = 0;
    const int OFF_PS = BB * MAX_DET * 4;           // 19200
    const int OFF_PL = OFF_PS + BB * MAX_DET;      // 24000
    const int OFF_PV = OFF_PL + BB * MAX_DET;      // 28800
    const int OFF_TB = OFF_PV + BB * MAX_DET;      // 33600
    const int OFF_TS = OFF_TB + BB * M_TGT * 4;    // 36800
    const int OFF_TL = OFF_TS + BB * M_TGT;        // 37600
    const int OFF_TV = OFF_TL + BB * M_TGT;        // 38400

    for (int i = tid; i < MAX_DET; i += nt) {
        bool kp = (i < nval) && ((s_keepw[i >> 5] >> (i & 31)) & 1u);
        float* pb = out + OFF_PB + ((size_t)b * MAX_DET + i) * 4;
        pb[0] = kp ? t_box[i][0] : 0.0f;
        pb[1] = kp ? t_box[i][1] : 0.0f;
        pb[2] = kp ? t_box[i][2] : 0.0f;
        pb[3] = kp ? t_box[i][3] : 0.0f;
        out[OFF_PS + b * MAX_DET + i] = kp ? t_score[i] : 0.0f;
        out[OFF_PL + b * MAX_DET + i] = kp ? (float)(t_meta[i] >> 16) : -1.0f;
        out[OFF_PV + b * MAX_DET + i] = kp ? 1.0f : 0.0f;
    }

    // targets
    int L = tlen[b];
    for (int m = tid; m < M_TGT; m += nt) {
        const float* q = tgt + ((size_t)b * M_TGT + m) * 6;
        bool v = (m < L);
        float cx = q[0], cy = q[1], w = q[2], h = q[3], sc = q[4], lb = q[5];
        float x1 = cx - 0.5f * w;
        float y1 = cy - 0.5f * h;
        float* tb = out + OFF_TB + ((size_t)b * M_TGT + m) * 4;
        tb[0] = v ? x1 : 0.0f;
        tb[1] = v ? y1 : 0.0f;
        tb[2] = v ? (x1 + w) : 0.0f;
        tb[3] = v ? (y1 + h) : 0.0f;
        out[OFF_TS + b * M_TGT + m] = v ? sc : 0.0f;
        out[OFF_TL + b * M_TGT + m] = v ? lb : -1.0f;
        out[OFF_TV + b * M_TGT + m] = v ? 1.0f : 0.0f;
    }
}

extern "C" void kernel_launch(void* const* d_in, const int* in_sizes, int n_in,
                              void* d_out, int out_size) {
    const float* preds = (const float*)d_in[0];
    const float* tgt   = (const float*)d_in[1];
    const int*   tlen  = (const int*)d_in[2];
    float* out = (float*)d_out;

    void* p_cnt = nullptr;
    void* p_hist = nullptr;
    cudaGetSymbolAddress(&p_cnt,  g_cand_count);
    cudaGetSymbolAddress(&p_hist, g_hist);
    cudaMemsetAsync(p_cnt,  0, sizeof(int) * BB);
    cudaMemsetAsync(p_hist, 0, sizeof(int) * BB * NBINS);

    score_kernel<<<(BB * NN) / ANCH_PER_BLK, SCORE_THREADS>>>(preds);  // 3150 blocks
    select_nms_kernel<<<BB, NMS_THREADS>>>(preds, tgt, tlen, out);
}